// round 10
// baseline (speedup 1.0000x reference)
#include <cuda_runtime.h>
#include <cuda_fp16.h>
#include <math.h>

#define NPG   286      // real nodes per graph
#define NPGP  287      // + dummy node
#define EPG   4000     // real edges per graph
#define NGRAPH 8192
#define THREADS 512
#define EPT   8        // padded edges per thread (4096 total)
#define NREAL (EPG / EPT)   // 500 threads carry real edges

__device__ __forceinline__ void gather_layer(const unsigned* __restrict__ s_csr,
                                             const unsigned* __restrict__ s_fxy,
                                             const float*    __restrict__ s_fz,
                                             __half2* __restrict__ s_axy,
                                             float*   __restrict__ s_az,
                                             int tid)
{
    const uint4* cp = (const uint4*)s_csr + tid * 2;
    uint4 c0 = cp[0];

    int cur, s;
    float ax, ay, az;
    {
        unsigned e = c0.x;
        cur = (int)(e >> 16); s = (int)(e & 0xFFFFu);
        unsigned pxy = s_fxy[s];
        float2 f2 = __half22float2(*(const __half2*)&pxy);
        ax = f2.x; ay = f2.y; az = s_fz[s];
    }
    #define GB(EV)                                                        \
    {                                                                     \
        unsigned e = (EV);                                                \
        int d = (int)(e >> 16);                                           \
        s = (int)(e & 0xFFFFu);                                           \
        unsigned pxy = s_fxy[s];                                          \
        float2 f2 = __half22float2(*(const __half2*)&pxy);                \
        float vz = s_fz[s];                                               \
        if (d != cur) {                                                   \
            atomicAdd(&s_axy[cur], __floats2half2_rn(ax, ay));            \
            atomicAdd(&s_az[cur], az);                                    \
            cur = d; ax = f2.x; ay = f2.y; az = vz;                       \
        } else { ax += f2.x; ay += f2.y; az += vz; }                      \
    }
    GB(c0.y) GB(c0.z) GB(c0.w)
    uint4 c1 = cp[1];
    GB(c1.x) GB(c1.y) GB(c1.z) GB(c1.w)
    #undef GB
    atomicAdd(&s_axy[cur], __floats2half2_rn(ax, ay));
    atomicAdd(&s_az[cur], az);
}

__global__ __launch_bounds__(THREADS)
void gnn_kernel(const float* __restrict__ feat,
                const int*   __restrict__ src,
                const int*   __restrict__ dst,
                const float* __restrict__ W1, const float* __restrict__ b1,
                const float* __restrict__ W2, const float* __restrict__ b2,
                const float* __restrict__ Wfc, const float* __restrict__ bfc,
                float* __restrict__ out)
{
    __shared__ unsigned int s_csr[EPT * THREADS];   // 4096: low16=src, high16=dst, sorted by dst
    __shared__ unsigned int s_fxy[NPGP];            // half2 (x, y), pre-scaled
    __shared__ float        s_fz [NPGP];            // z fp32, pre-scaled
    __shared__ __half2      s_axy[NPGP];            // accumulator (x, y)
    __shared__ float        s_az [NPGP];            // accumulator z
    __shared__ int   s_degin [NPGP];
    __shared__ int   s_degout[NPGP];
    __shared__ int   s_cur   [NPGP];
    __shared__ float s_nin [NPGP];
    __shared__ float s_nout[NPGP];
    __shared__ int   s_wsum[16];
    __shared__ float s_red[16];

    const int g    = blockIdx.x;
    const int tid  = threadIdx.x;
    const int lane = tid & 31;
    const int warp = tid >> 5;
    const int base = g * NPG;
    const int* __restrict__ srcp = src + (long long)g * EPG;
    const int* __restrict__ dstp = dst + (long long)g * EPG;

    // ---- init counters ----
    if (tid < NPGP) { s_degin[tid] = 0; s_degout[tid] = 0; }
    __syncthreads();

    // ---- degree count: read edges from global (int4, coalesced) ----
    if (tid < NREAL) {
        const int4* sp = (const int4*)srcp + tid * 2;
        const int4* dp = (const int4*)dstp + tid * 2;
        int4 s0 = sp[0], s1 = sp[1];
        int4 d0 = dp[0], d1 = dp[1];
        int ss[EPT] = { s0.x, s0.y, s0.z, s0.w, s1.x, s1.y, s1.z, s1.w };
        int dd[EPT] = { d0.x, d0.y, d0.z, d0.w, d1.x, d1.y, d1.z, d1.w };
        #pragma unroll
        for (int i = 0; i < EPT; i++) {
            atomicAdd(&s_degout[ss[i] - base], 1);
            atomicAdd(&s_degin [dd[i] - base], 1);
        }
    } else {
        // 12 dummy threads: 8 dummy edges each -> node NPG
        atomicAdd(&s_degin [NPG], EPT);
        atomicAdd(&s_degout[NPG], EPT);
    }
    __syncthreads();

    // ---- warp-shfl scan of deg_in -> exclusive offsets + norms ----
    int degv = (tid < NPGP) ? s_degin[tid] : 0;
    int v = degv;
    #pragma unroll
    for (int o = 1; o < 32; o <<= 1) {
        int n = __shfl_up_sync(0xFFFFFFFFu, v, o);
        if (lane >= o) v += n;
    }
    if (lane == 31) s_wsum[warp] = v;
    __syncthreads();
    if (warp == 0 && lane < 16) {
        int w = s_wsum[lane];
        #pragma unroll
        for (int o = 1; o < 16; o <<= 1) {
            int n = __shfl_up_sync(0xFFFFu, w, o);
            if (lane >= o) w += n;
        }
        s_wsum[lane] = w;
    }
    __syncthreads();
    if (tid < NPGP) {
        s_cur[tid]  = v + (warp ? s_wsum[warp - 1] : 0) - degv;  // exclusive offset
        s_nin[tid]  = rsqrtf(fmaxf((float)degv, 1.0f));
        s_nout[tid] = rsqrtf(fmaxf((float)s_degout[tid], 1.0f));
    }
    __syncthreads();

    // ---- counting-sort scatter: re-read edges from global (L2-hot) ----
    if (tid < NREAL) {
        const int4* sp = (const int4*)srcp + tid * 2;
        const int4* dp = (const int4*)dstp + tid * 2;
        int4 s0 = sp[0], s1 = sp[1];
        int4 d0 = dp[0], d1 = dp[1];
        int ss[EPT] = { s0.x, s0.y, s0.z, s0.w, s1.x, s1.y, s1.z, s1.w };
        int dd[EPT] = { d0.x, d0.y, d0.z, d0.w, d1.x, d1.y, d1.z, d1.w };
        #pragma unroll
        for (int i = 0; i < EPT; i++) {
            int s = ss[i] - base;
            int d = dd[i] - base;
            int pos = atomicAdd(&s_cur[d], 1);
            s_csr[pos] = (unsigned)s | ((unsigned)d << 16);
        }
    } else {
        const unsigned de = (unsigned)NPG | ((unsigned)NPG << 16);
        #pragma unroll
        for (int i = 0; i < EPT; i++) {
            int pos = atomicAdd(&s_cur[NPG], 1);
            s_csr[pos] = de;
        }
    }

    // ---- load features, scale by norm_out, pack (x,y)->half2; zero accums ----
    if (tid < NPGP) {
        if (tid < NPG) {
            const float* fp = feat + (long long)(base + tid) * 3;
            float no = s_nout[tid];
            __half2 h = __floats2half2_rn(fp[0] * no, fp[1] * no);
            s_fxy[tid] = *(unsigned*)&h;
            s_fz[tid]  = fp[2] * no;
        } else {
            s_fxy[tid] = 0u;
            s_fz[tid]  = 0.f;
        }
        s_axy[tid] = __floats2half2_rn(0.f, 0.f);
        s_az[tid]  = 0.f;
    }
    __syncthreads();

    // ===================== layer 1 gather (vectorized CSR) =====================
    gather_layer(s_csr, s_fxy, s_fz, s_axy, s_az, tid);
    __syncthreads();

    // ---- layer 1 node transform ----
    if (tid < NPGP) {
        if (tid < NPG) {
            float ni = s_nin[tid];
            float2 a2 = __half22float2(s_axy[tid]);
            float ax = a2.x * ni, ay = a2.y * ni, az = s_az[tid] * ni;
            float o0 = fmaxf(fmaf(ax, __ldg(W1+0), fmaf(ay, __ldg(W1+3), fmaf(az, __ldg(W1+6), __ldg(b1+0)))), 0.f);
            float o1 = fmaxf(fmaf(ax, __ldg(W1+1), fmaf(ay, __ldg(W1+4), fmaf(az, __ldg(W1+7), __ldg(b1+1)))), 0.f);
            float o2 = fmaxf(fmaf(ax, __ldg(W1+2), fmaf(ay, __ldg(W1+5), fmaf(az, __ldg(W1+8), __ldg(b1+2)))), 0.f);
            float no = s_nout[tid];
            __half2 h = __floats2half2_rn(o0 * no, o1 * no);
            s_fxy[tid] = *(unsigned*)&h;
            s_fz[tid]  = o2 * no;
        } else {
            s_fxy[tid] = 0u;
            s_fz[tid]  = 0.f;
        }
        s_axy[tid] = __floats2half2_rn(0.f, 0.f);
        s_az[tid]  = 0.f;
    }
    __syncthreads();

    // ===================== layer 2 gather =====================
    gather_layer(s_csr, s_fxy, s_fz, s_axy, s_az, tid);
    __syncthreads();

    // ---- layer 2 node transform: raw outputs into scratch ----
    if (tid < NPG) {
        float ni = s_nin[tid];
        float2 a2 = __half22float2(s_axy[tid]);
        float ax = a2.x * ni, ay = a2.y * ni, az = s_az[tid] * ni;
        float o0 = fmaxf(fmaf(ax, __ldg(W2+0), fmaf(ay, __ldg(W2+3), fmaf(az, __ldg(W2+6), __ldg(b2+0)))), 0.f);
        float o1 = fmaxf(fmaf(ax, __ldg(W2+1), fmaf(ay, __ldg(W2+4), fmaf(az, __ldg(W2+7), __ldg(b2+1)))), 0.f);
        float o2 = fmaxf(fmaf(ax, __ldg(W2+2), fmaf(ay, __ldg(W2+5), fmaf(az, __ldg(W2+8), __ldg(b2+2)))), 0.f);
        s_nin[tid]  = o0;
        s_nout[tid] = o1;
        s_fz[tid]   = o2;
    }
    __syncthreads();

    // ---- FC: out[g] = sigmoid( sum_k x2_flat[k] * Wfc[k] + bfc ) ----
    float acc = 0.f;
    for (int k = tid; k < NPG * 3; k += THREADS) {
        int i = k / 3;
        int j = k - 3 * i;
        float val = (j == 0) ? s_nin[i] : (j == 1) ? s_nout[i] : s_fz[i];
        acc += val * __ldg(Wfc + k);
    }
    #pragma unroll
    for (int o = 16; o > 0; o >>= 1) acc += __shfl_down_sync(0xFFFFFFFFu, acc, o);
    if (lane == 0) s_red[warp] = acc;
    __syncthreads();
    if (tid < 32) {
        float vv = (tid < (THREADS / 32)) ? s_red[tid] : 0.f;
        #pragma unroll
        for (int o = 8; o > 0; o >>= 1) vv += __shfl_down_sync(0xFFFFFFFFu, vv, o);
        if (tid == 0) {
            float z = vv + __ldg(bfc);
            out[g] = 1.0f / (1.0f + expf(-z));
        }
    }
}

extern "C" void kernel_launch(void* const* d_in, const int* in_sizes, int n_in,
                              void* d_out, int out_size)
{
    const float* feat = (const float*)d_in[0];
    const int*   src  = (const int*)  d_in[1];
    const int*   dst  = (const int*)  d_in[2];
    const float* W1   = (const float*)d_in[3];
    const float* b1   = (const float*)d_in[4];
    const float* W2   = (const float*)d_in[5];
    const float* b2   = (const float*)d_in[6];
    const float* Wfc  = (const float*)d_in[7];
    const float* bfc  = (const float*)d_in[8];

    int ngraph = out_size > 0 ? out_size : NGRAPH;
    gnn_kernel<<<ngraph, THREADS>>>(feat, src, dst, W1, b1, W2, b2, Wfc, bfc,
                                    (float*)d_out);
}

// round 11
// speedup vs baseline: 1.0113x; 1.0113x over previous
#include <cuda_runtime.h>
#include <cuda_fp16.h>
#include <math.h>

#define NPG   286      // real nodes per graph
#define NPGP  287      // + dummy node
#define EPG   4000     // real edges per graph
#define NGRAPH 8192
#define THREADS 512
#define EPT   8        // padded edges per thread (4096 total)
#define NREAL (EPG / EPT)   // 500 threads carry real edges

__device__ __forceinline__ void gather_layer(const unsigned* __restrict__ s_csr,
                                             const uint2*    __restrict__ s_f,
                                             __half2* __restrict__ s_axy,
                                             float*   __restrict__ s_az,
                                             int tid)
{
    const uint4* cp = (const uint4*)s_csr + tid * 2;
    uint4 c0 = cp[0];

    int cur, s;
    float ax, ay, az;
    {
        unsigned e = c0.x;
        cur = (int)(e >> 16); s = (int)(e & 0xFFFFu);
        uint2 p = s_f[s];
        float2 f2 = __half22float2(*(const __half2*)&p.x);
        ax = f2.x; ay = f2.y; az = __uint_as_float(p.y);
    }
    #define GB(EV)                                                        \
    {                                                                     \
        unsigned e = (EV);                                                \
        int d = (int)(e >> 16);                                           \
        s = (int)(e & 0xFFFFu);                                           \
        uint2 p = s_f[s];                                                 \
        float2 f2 = __half22float2(*(const __half2*)&p.x);                \
        float vz = __uint_as_float(p.y);                                  \
        if (d != cur) {                                                   \
            atomicAdd(&s_axy[cur], __floats2half2_rn(ax, ay));            \
            atomicAdd(&s_az[cur], az);                                    \
            cur = d; ax = f2.x; ay = f2.y; az = vz;                       \
        } else { ax += f2.x; ay += f2.y; az += vz; }                      \
    }
    GB(c0.y) GB(c0.z) GB(c0.w)
    uint4 c1 = cp[1];
    GB(c1.x) GB(c1.y) GB(c1.z) GB(c1.w)
    #undef GB
    atomicAdd(&s_axy[cur], __floats2half2_rn(ax, ay));
    atomicAdd(&s_az[cur], az);
}

__global__ __launch_bounds__(THREADS)
void gnn_kernel(const float* __restrict__ feat,
                const int*   __restrict__ src,
                const int*   __restrict__ dst,
                const float* __restrict__ W1, const float* __restrict__ b1,
                const float* __restrict__ W2, const float* __restrict__ b2,
                const float* __restrict__ Wfc, const float* __restrict__ bfc,
                float* __restrict__ out)
{
    __shared__ unsigned int s_csr[EPT * THREADS];   // 4096: low16=src, high16=dst, sorted by dst
    __shared__ uint2        s_f  [NPGP];            // {half2 (x,y), float z}, pre-scaled
    __shared__ __half2      s_axy[NPGP];            // accumulator (x, y)
    __shared__ float        s_az [NPGP];            // accumulator z
    __shared__ int   s_cnt   [NPGP];                // pass1 rank counter -> ends as deg_in
    __shared__ int   s_degout[NPGP];
    __shared__ int   s_off   [NPGP];                // exclusive CSR offsets
    __shared__ float s_nin [NPGP];
    __shared__ float s_nout[NPGP];
    __shared__ int   s_wsum[16];
    __shared__ float s_red[16];

    const int g    = blockIdx.x;
    const int tid  = threadIdx.x;
    const int lane = tid & 31;
    const int warp = tid >> 5;
    const int base = g * NPG;
    const int* __restrict__ srcp = src + (long long)g * EPG;
    const int* __restrict__ dstp = dst + (long long)g * EPG;

    // ---- init counters ----
    if (tid < NPGP) { s_cnt[tid] = 0; s_degout[tid] = 0; }
    __syncthreads();

    // ---- pass 1: rank+count. r = old count = this edge's rank within dst bucket ----
    unsigned long long pos = 0ull;   // 8 packed byte-ranks (max degree << 256)
    if (tid < NREAL) {
        const int4* sp = (const int4*)srcp + tid * 2;
        const int4* dp = (const int4*)dstp + tid * 2;
        int4 s0 = sp[0], s1 = sp[1];
        int4 d0 = dp[0], d1 = dp[1];
        int ss[EPT] = { s0.x, s0.y, s0.z, s0.w, s1.x, s1.y, s1.z, s1.w };
        int dd[EPT] = { d0.x, d0.y, d0.z, d0.w, d1.x, d1.y, d1.z, d1.w };
        #pragma unroll
        for (int i = 0; i < EPT; i++) {
            atomicAdd(&s_degout[ss[i] - base], 1);
            int r = atomicAdd(&s_cnt[dd[i] - base], 1);
            pos |= (unsigned long long)(unsigned)(r & 0xFF) << (8 * i);
        }
    } else {
        int r = atomicAdd(&s_cnt[NPG], EPT);          // 8 dummy edges -> node NPG
        atomicAdd(&s_degout[NPG], EPT);
        #pragma unroll
        for (int i = 0; i < EPT; i++)
            pos |= (unsigned long long)(unsigned)((r + i) & 0xFF) << (8 * i);
    }
    __syncthreads();

    // ---- warp-shfl scan of deg_in -> exclusive offsets + norms ----
    int degv = (tid < NPGP) ? s_cnt[tid] : 0;
    int v = degv;
    #pragma unroll
    for (int o = 1; o < 32; o <<= 1) {
        int n = __shfl_up_sync(0xFFFFFFFFu, v, o);
        if (lane >= o) v += n;
    }
    if (lane == 31) s_wsum[warp] = v;
    __syncthreads();
    if (warp == 0 && lane < 16) {
        int w = s_wsum[lane];
        #pragma unroll
        for (int o = 1; o < 16; o <<= 1) {
            int n = __shfl_up_sync(0xFFFFu, w, o);
            if (lane >= o) w += n;
        }
        s_wsum[lane] = w;
    }
    __syncthreads();
    if (tid < NPGP) {
        s_off[tid]  = v + (warp ? s_wsum[warp - 1] : 0) - degv;  // exclusive offset
        s_nin[tid]  = rsqrtf(fmaxf((float)degv, 1.0f));
        s_nout[tid] = rsqrtf(fmaxf((float)s_degout[tid], 1.0f));
    }
    __syncthreads();

    // ---- pass 2: atomic-free scatter via precomputed ranks (re-read edges, L2-hot) ----
    if (tid < NREAL) {
        const int4* sp = (const int4*)srcp + tid * 2;
        const int4* dp = (const int4*)dstp + tid * 2;
        int4 s0 = sp[0], s1 = sp[1];
        int4 d0 = dp[0], d1 = dp[1];
        int ss[EPT] = { s0.x, s0.y, s0.z, s0.w, s1.x, s1.y, s1.z, s1.w };
        int dd[EPT] = { d0.x, d0.y, d0.z, d0.w, d1.x, d1.y, d1.z, d1.w };
        #pragma unroll
        for (int i = 0; i < EPT; i++) {
            int s = ss[i] - base;
            int d = dd[i] - base;
            int r = (int)((pos >> (8 * i)) & 0xFFull);
            s_csr[s_off[d] + r] = (unsigned)s | ((unsigned)d << 16);
        }
    } else {
        const unsigned de = (unsigned)NPG | ((unsigned)NPG << 16);
        int o = s_off[NPG];
        #pragma unroll
        for (int i = 0; i < EPT; i++) {
            int r = (int)((pos >> (8 * i)) & 0xFFull);
            s_csr[o + r] = de;
        }
    }

    // ---- load features, scale by norm_out, pack {half2(x,y), z}; zero accums ----
    if (tid < NPGP) {
        if (tid < NPG) {
            const float* fp = feat + (long long)(base + tid) * 3;
            float no = s_nout[tid];
            __half2 h = __floats2half2_rn(fp[0] * no, fp[1] * no);
            s_f[tid] = make_uint2(*(unsigned*)&h, __float_as_uint(fp[2] * no));
        } else {
            s_f[tid] = make_uint2(0u, 0u);
        }
        s_axy[tid] = __floats2half2_rn(0.f, 0.f);
        s_az[tid]  = 0.f;
    }
    __syncthreads();

    // ===================== layer 1 gather =====================
    gather_layer(s_csr, s_f, s_axy, s_az, tid);
    __syncthreads();

    // ---- layer 1 node transform ----
    if (tid < NPGP) {
        if (tid < NPG) {
            float ni = s_nin[tid];
            float2 a2 = __half22float2(s_axy[tid]);
            float ax = a2.x * ni, ay = a2.y * ni, az = s_az[tid] * ni;
            float o0 = fmaxf(fmaf(ax, __ldg(W1+0), fmaf(ay, __ldg(W1+3), fmaf(az, __ldg(W1+6), __ldg(b1+0)))), 0.f);
            float o1 = fmaxf(fmaf(ax, __ldg(W1+1), fmaf(ay, __ldg(W1+4), fmaf(az, __ldg(W1+7), __ldg(b1+1)))), 0.f);
            float o2 = fmaxf(fmaf(ax, __ldg(W1+2), fmaf(ay, __ldg(W1+5), fmaf(az, __ldg(W1+8), __ldg(b1+2)))), 0.f);
            float no = s_nout[tid];
            __half2 h = __floats2half2_rn(o0 * no, o1 * no);
            s_f[tid] = make_uint2(*(unsigned*)&h, __float_as_uint(o2 * no));
        } else {
            s_f[tid] = make_uint2(0u, 0u);
        }
        s_axy[tid] = __floats2half2_rn(0.f, 0.f);
        s_az[tid]  = 0.f;
    }
    __syncthreads();

    // ===================== layer 2 gather =====================
    gather_layer(s_csr, s_f, s_axy, s_az, tid);
    __syncthreads();

    // ---- layer 2 node transform: raw outputs into scratch ----
    if (tid < NPG) {
        float ni = s_nin[tid];
        float2 a2 = __half22float2(s_axy[tid]);
        float ax = a2.x * ni, ay = a2.y * ni, az = s_az[tid] * ni;
        float o0 = fmaxf(fmaf(ax, __ldg(W2+0), fmaf(ay, __ldg(W2+3), fmaf(az, __ldg(W2+6), __ldg(b2+0)))), 0.f);
        float o1 = fmaxf(fmaf(ax, __ldg(W2+1), fmaf(ay, __ldg(W2+4), fmaf(az, __ldg(W2+7), __ldg(b2+1)))), 0.f);
        float o2 = fmaxf(fmaf(ax, __ldg(W2+2), fmaf(ay, __ldg(W2+5), fmaf(az, __ldg(W2+8), __ldg(b2+2)))), 0.f);
        s_nin[tid]  = o0;
        s_nout[tid] = o1;
        s_az[tid]   = o2;
    }
    __syncthreads();

    // ---- FC: out[g] = sigmoid( sum_k x2_flat[k] * Wfc[k] + bfc ) ----
    float acc = 0.f;
    for (int k = tid; k < NPG * 3; k += THREADS) {
        int i = k / 3;
        int j = k - 3 * i;
        float val = (j == 0) ? s_nin[i] : (j == 1) ? s_nout[i] : s_az[i];
        acc += val * __ldg(Wfc + k);
    }
    #pragma unroll
    for (int o = 16; o > 0; o >>= 1) acc += __shfl_down_sync(0xFFFFFFFFu, acc, o);
    if (lane == 0) s_red[warp] = acc;
    __syncthreads();
    if (tid < 32) {
        float vv = (tid < (THREADS / 32)) ? s_red[tid] : 0.f;
        #pragma unroll
        for (int o = 8; o > 0; o >>= 1) vv += __shfl_down_sync(0xFFFFFFFFu, vv, o);
        if (tid == 0) {
            float z = vv + __ldg(bfc);
            out[g] = 1.0f / (1.0f + expf(-z));
        }
    }
}

extern "C" void kernel_launch(void* const* d_in, const int* in_sizes, int n_in,
                              void* d_out, int out_size)
{
    const float* feat = (const float*)d_in[0];
    const int*   src  = (const int*)  d_in[1];
    const int*   dst  = (const int*)  d_in[2];
    const float* W1   = (const float*)d_in[3];
    const float* b1   = (const float*)d_in[4];
    const float* W2   = (const float*)d_in[5];
    const float* b2   = (const float*)d_in[6];
    const float* Wfc  = (const float*)d_in[7];
    const float* bfc  = (const float*)d_in[8];

    int ngraph = out_size > 0 ? out_size : NGRAPH;
    gnn_kernel<<<ngraph, THREADS>>>(feat, src, dst, W1, b1, W2, b2, Wfc, bfc,
                                    (float*)d_out);
}

// round 12
// speedup vs baseline: 1.0753x; 1.0633x over previous
#include <cuda_runtime.h>
#include <cuda_fp16.h>
#include <math.h>

#define NPG   286      // real nodes per graph
#define NPGP  287      // + dummy node
#define EPG   4000     // real edges per graph
#define NGRAPH 8192
#define THREADS 512
#define EPT   8        // padded edges per thread (4096 total)
#define NREAL (EPG / EPT)   // 500 threads carry real edges

__device__ __forceinline__ void gather_layer(const unsigned* __restrict__ s_csr,
                                             const uint2*    __restrict__ s_f,
                                             __half2* __restrict__ s_axy,
                                             float*   __restrict__ s_az,
                                             int tid)
{
    const uint4* cp = (const uint4*)s_csr + tid * 2;
    uint4 c0 = cp[0];

    int cur, s;
    float ax, ay, az;
    {
        unsigned e = c0.x;
        cur = (int)(e >> 16); s = (int)(e & 0xFFFFu);
        uint2 p = s_f[s];
        float2 f2 = __half22float2(*(const __half2*)&p.x);
        ax = f2.x; ay = f2.y; az = __uint_as_float(p.y);
    }
    #define GB(EV)                                                        \
    {                                                                     \
        unsigned e = (EV);                                                \
        int d = (int)(e >> 16);                                           \
        s = (int)(e & 0xFFFFu);                                           \
        uint2 p = s_f[s];                                                 \
        float2 f2 = __half22float2(*(const __half2*)&p.x);                \
        float vz = __uint_as_float(p.y);                                  \
        if (d != cur) {                                                   \
            atomicAdd(&s_axy[cur], __floats2half2_rn(ax, ay));            \
            atomicAdd(&s_az[cur], az);                                    \
            cur = d; ax = f2.x; ay = f2.y; az = vz;                       \
        } else { ax += f2.x; ay += f2.y; az += vz; }                      \
    }
    GB(c0.y) GB(c0.z) GB(c0.w)
    uint4 c1 = cp[1];
    GB(c1.x) GB(c1.y) GB(c1.z) GB(c1.w)
    #undef GB
    atomicAdd(&s_axy[cur], __floats2half2_rn(ax, ay));
    atomicAdd(&s_az[cur], az);
}

__global__ __launch_bounds__(THREADS, 4)
void gnn_kernel(const float* __restrict__ feat,
                const int*   __restrict__ src,
                const int*   __restrict__ dst,
                const float* __restrict__ W1, const float* __restrict__ b1,
                const float* __restrict__ W2, const float* __restrict__ b2,
                const float* __restrict__ Wfc, const float* __restrict__ bfc,
                float* __restrict__ out)
{
    __shared__ unsigned int s_csr[EPT * THREADS];   // 4096: low16=src, high16=dst, sorted by dst
    __shared__ uint2        s_f  [NPGP];            // {half2 (x,y), float z}, pre-scaled
    __shared__ __half2      s_axy[NPGP];            // accumulator (x, y)
    __shared__ float        s_az [NPGP];            // accumulator z
    __shared__ int   s_cnt   [NPGP];                // pass1 rank counter -> ends as deg_in
    __shared__ int   s_degout[NPGP];
    __shared__ int   s_off   [NPGP];                // exclusive CSR offsets
    __shared__ float s_nin [NPGP];
    __shared__ float s_nout[NPGP];
    __shared__ int   s_wsum[16];
    __shared__ float s_red[16];

    const int g    = blockIdx.x;
    const int tid  = threadIdx.x;
    const int lane = tid & 31;
    const int warp = tid >> 5;
    const int base = g * NPG;
    const int* __restrict__ srcp = src + (long long)g * EPG;
    const int* __restrict__ dstp = dst + (long long)g * EPG;

    // ---- init counters ----
    if (tid < NPGP) { s_cnt[tid] = 0; s_degout[tid] = 0; }
    __syncthreads();

    // ---- single global read: edges -> registers; pass 1: rank+count atomics ----
    unsigned er[EPT];                // packed (s | d<<16), kept through scatter
    unsigned long long pos = 0ull;   // 8 packed byte-ranks (max degree << 256)
    if (tid < NREAL) {
        const int4* sp = (const int4*)srcp + tid * 2;
        const int4* dp = (const int4*)dstp + tid * 2;
        int4 s0 = sp[0], s1 = sp[1];
        int4 d0 = dp[0], d1 = dp[1];
        int ss[EPT] = { s0.x, s0.y, s0.z, s0.w, s1.x, s1.y, s1.z, s1.w };
        int dd[EPT] = { d0.x, d0.y, d0.z, d0.w, d1.x, d1.y, d1.z, d1.w };
        #pragma unroll
        for (int i = 0; i < EPT; i++) {
            int s = ss[i] - base;
            int d = dd[i] - base;
            er[i] = (unsigned)s | ((unsigned)d << 16);
            atomicAdd(&s_degout[s], 1);
            int r = atomicAdd(&s_cnt[d], 1);
            pos |= (unsigned long long)(unsigned)(r & 0xFF) << (8 * i);
        }
    } else {
        const unsigned de = (unsigned)NPG | ((unsigned)NPG << 16);
        int r = atomicAdd(&s_cnt[NPG], EPT);          // 8 dummy edges -> node NPG
        atomicAdd(&s_degout[NPG], EPT);
        #pragma unroll
        for (int i = 0; i < EPT; i++) {
            er[i] = de;
            pos |= (unsigned long long)(unsigned)((r + i) & 0xFF) << (8 * i);
        }
    }
    __syncthreads();

    // ---- warp-shfl scan of deg_in -> exclusive offsets + norms ----
    int degv = (tid < NPGP) ? s_cnt[tid] : 0;
    int v = degv;
    #pragma unroll
    for (int o = 1; o < 32; o <<= 1) {
        int n = __shfl_up_sync(0xFFFFFFFFu, v, o);
        if (lane >= o) v += n;
    }
    if (lane == 31) s_wsum[warp] = v;
    __syncthreads();
    if (warp == 0 && lane < 16) {
        int w = s_wsum[lane];
        #pragma unroll
        for (int o = 1; o < 16; o <<= 1) {
            int n = __shfl_up_sync(0xFFFFu, w, o);
            if (lane >= o) w += n;
        }
        s_wsum[lane] = w;
    }
    __syncthreads();
    if (tid < NPGP) {
        s_off[tid]  = v + (warp ? s_wsum[warp - 1] : 0) - degv;  // exclusive offset
        s_nin[tid]  = rsqrtf(fmaxf((float)degv, 1.0f));
        s_nout[tid] = rsqrtf(fmaxf((float)s_degout[tid], 1.0f));
    }
    __syncthreads();

    // ---- pass 2: atomic-free scatter, edges straight from registers ----
    #pragma unroll
    for (int i = 0; i < EPT; i++) {
        int d = (int)(er[i] >> 16);
        int r = (int)((pos >> (8 * i)) & 0xFFull);
        s_csr[s_off[d] + r] = er[i];
    }

    // ---- load features, scale by norm_out, pack {half2(x,y), z}; zero accums ----
    if (tid < NPGP) {
        if (tid < NPG) {
            const float* fp = feat + (long long)(base + tid) * 3;
            float no = s_nout[tid];
            __half2 h = __floats2half2_rn(fp[0] * no, fp[1] * no);
            s_f[tid] = make_uint2(*(unsigned*)&h, __float_as_uint(fp[2] * no));
        } else {
            s_f[tid] = make_uint2(0u, 0u);
        }
        s_axy[tid] = __floats2half2_rn(0.f, 0.f);
        s_az[tid]  = 0.f;
    }
    __syncthreads();

    // ===================== layer 1 gather =====================
    gather_layer(s_csr, s_f, s_axy, s_az, tid);
    __syncthreads();

    // ---- layer 1 node transform ----
    if (tid < NPGP) {
        if (tid < NPG) {
            float ni = s_nin[tid];
            float2 a2 = __half22float2(s_axy[tid]);
            float ax = a2.x * ni, ay = a2.y * ni, az = s_az[tid] * ni;
            float o0 = fmaxf(fmaf(ax, __ldg(W1+0), fmaf(ay, __ldg(W1+3), fmaf(az, __ldg(W1+6), __ldg(b1+0)))), 0.f);
            float o1 = fmaxf(fmaf(ax, __ldg(W1+1), fmaf(ay, __ldg(W1+4), fmaf(az, __ldg(W1+7), __ldg(b1+1)))), 0.f);
            float o2 = fmaxf(fmaf(ax, __ldg(W1+2), fmaf(ay, __ldg(W1+5), fmaf(az, __ldg(W1+8), __ldg(b1+2)))), 0.f);
            float no = s_nout[tid];
            __half2 h = __floats2half2_rn(o0 * no, o1 * no);
            s_f[tid] = make_uint2(*(unsigned*)&h, __float_as_uint(o2 * no));
        } else {
            s_f[tid] = make_uint2(0u, 0u);
        }
        s_axy[tid] = __floats2half2_rn(0.f, 0.f);
        s_az[tid]  = 0.f;
    }
    __syncthreads();

    // ===================== layer 2 gather =====================
    gather_layer(s_csr, s_f, s_axy, s_az, tid);
    __syncthreads();

    // ---- layer 2 node transform: raw outputs into scratch ----
    if (tid < NPG) {
        float ni = s_nin[tid];
        float2 a2 = __half22float2(s_axy[tid]);
        float ax = a2.x * ni, ay = a2.y * ni, az = s_az[tid] * ni;
        float o0 = fmaxf(fmaf(ax, __ldg(W2+0), fmaf(ay, __ldg(W2+3), fmaf(az, __ldg(W2+6), __ldg(b2+0)))), 0.f);
        float o1 = fmaxf(fmaf(ax, __ldg(W2+1), fmaf(ay, __ldg(W2+4), fmaf(az, __ldg(W2+7), __ldg(b2+1)))), 0.f);
        float o2 = fmaxf(fmaf(ax, __ldg(W2+2), fmaf(ay, __ldg(W2+5), fmaf(az, __ldg(W2+8), __ldg(b2+2)))), 0.f);
        s_nin[tid]  = o0;
        s_nout[tid] = o1;
        s_az[tid]   = o2;
    }
    __syncthreads();

    // ---- FC: out[g] = sigmoid( sum_k x2_flat[k] * Wfc[k] + bfc ) ----
    float acc = 0.f;
    for (int k = tid; k < NPG * 3; k += THREADS) {
        int i = k / 3;
        int j = k - 3 * i;
        float val = (j == 0) ? s_nin[i] : (j == 1) ? s_nout[i] : s_az[i];
        acc += val * __ldg(Wfc + k);
    }
    #pragma unroll
    for (int o = 16; o > 0; o >>= 1) acc += __shfl_down_sync(0xFFFFFFFFu, acc, o);
    if (lane == 0) s_red[warp] = acc;
    __syncthreads();
    if (tid < 32) {
        float vv = (tid < (THREADS / 32)) ? s_red[tid] : 0.f;
        #pragma unroll
        for (int o = 8; o > 0; o >>= 1) vv += __shfl_down_sync(0xFFFFFFFFu, vv, o);
        if (tid == 0) {
            float z = vv + __ldg(bfc);
            out[g] = 1.0f / (1.0f + expf(-z));
        }
    }
}

extern "C" void kernel_launch(void* const* d_in, const int* in_sizes, int n_in,
                              void* d_out, int out_size)
{
    const float* feat = (const float*)d_in[0];
    const int*   src  = (const int*)  d_in[1];
    const int*   dst  = (const int*)  d_in[2];
    const float* W1   = (const float*)d_in[3];
    const float* b1   = (const float*)d_in[4];
    const float* W2   = (const float*)d_in[5];
    const float* b2   = (const float*)d_in[6];
    const float* Wfc  = (const float*)d_in[7];
    const float* bfc  = (const float*)d_in[8];

    int ngraph = out_size > 0 ? out_size : NGRAPH;
    gnn_kernel<<<ngraph, THREADS>>>(feat, src, dst, W1, b1, W2, b2, Wfc, bfc,
                                    (float*)d_out);
}